// round 2
// baseline (speedup 1.0000x reference)
#include <cuda_runtime.h>
#include <math.h>
#include <stdint.h>

#define MAXT_C 10000
#define MAXB_C 4096
#define TCHUNK 64

// Scratch (static __device__ arrays: no allocation allowed)
__device__ float   g_T2[MAXT_C];        // per-step death threshold: exp(logit_t) - eps
__device__ double  g_prefix[MAXT_C + 1];// prefix[k] = sum_{t<k} w_t
__device__ int     g_death[MAXB_C];     // first death step per lane (T if none)
__device__ int     g_tcut;              // no deaths possible for t >= g_tcut

// Exclusive block-wide scan (blockDim.x == 1024), fp64, no subtraction tricks.
__device__ __forceinline__ double block_scan_excl(double v, double& total, double* s_warp) {
    const unsigned FULL = 0xffffffffu;
    int lane = threadIdx.x & 31;
    int w    = threadIdx.x >> 5;
    double inc = v;
#pragma unroll
    for (int o = 1; o < 32; o <<= 1) {
        double n = __shfl_up_sync(FULL, inc, o);
        if (lane >= o) inc += n;
    }
    double exc = __shfl_up_sync(FULL, inc, 1);
    if (lane == 0) exc = 0.0;
    if (lane == 31) s_warp[w] = inc;
    __syncthreads();
    if (w == 0) {
        double x = s_warp[lane];
        double i2 = x;
#pragma unroll
        for (int o = 1; o < 32; o <<= 1) {
            double n = __shfl_up_sync(FULL, i2, o);
            if (lane >= o) i2 += n;
        }
        double e2 = __shfl_up_sync(FULL, i2, 1);
        if (lane == 0) e2 = 0.0;
        s_warp[lane] = e2;
        if (lane == 31) s_warp[32] = i2;
    }
    __syncthreads();
    exc += s_warp[w];
    total = s_warp[32];
    __syncthreads();   // protect s_warp before next call
    return exc;
}

// Kernel 1: scalar (batch-independent) precompute over T steps.
// Three fused prefix sums: logw, logp, and the reward prefix. Also computes
// g_tcut (last step where a death is possible) and initializes g_death.
__global__ void __launch_bounds__(1024) k_precompute(const float* __restrict__ acts, int T, int B) {
    __shared__ double s_warp[33];
    __shared__ int s_imax[32];
    int tid = threadIdx.x;

    for (int i = tid; i < B; i += 1024) g_death[i] = T;

    // Constants exactly as the reference builds them (python double -> fp32 weak-type use)
    const float LOG_GAMMA_F = (float)log(1.02);
    const float ALPHA_F     = (float)(log(0.99) / 1000.0);
    const float INIT_LOGW_F = (float)log(0.248);
    const float INIT_LOGP_F = (float)log(0.001);

    double carryW = (double)INIT_LOGW_F;  // logw entering step t (exclusive)
    double carryP = (double)INIT_LOGP_F;  // logp entering step t (exclusive)
    double carryS = 0.0;                  // reward prefix
    int tmax = 0;

    int nch = (T + 1023) >> 10;
    for (int ch = 0; ch < nch; ch++) {
        int i = (ch << 10) + tid;
        bool valid = (i < T);
        float a = valid ? acts[i] : 0.0f;
        float f = expf(a);
        float c = valid ? (LOG_GAMMA_F + logf(1.0f - f)) : 0.0f;  // logw increment at step i

        double tot;
        double W = block_scan_excl(valid ? (double)c : 0.0, tot, s_warp) + carryW;
        carryW += tot;
        float Wf = (float)W;                 // logw BEFORE step i (what logp update uses)

        float df = valid ? (ALPHA_F * f * expf(Wf)) : 0.0f;
        double P = block_scan_excl((double)df, tot, s_warp) + carryP;
        carryP += tot;
        float Pf = (float)P;                 // logp entering step i (what gumbel uses)

        float logit = Pf - log1pf(-expf(Pf));
        float thr = expf(logit);             // death condition: ratio + eps < thr
        float wv = valid ? expf((Wf + c) / 1000.0f) : 0.0f;  // exp(new_logw / TEMPERATURE)

        double pre = block_scan_excl((double)wv, tot, s_warp) + carryS;
        carryS += tot;

        if (valid) {
            g_T2[i] = thr - 1e-12f;
            g_prefix[i] = pre;
            if (logit >= -25.0f) tmax = max(tmax, i + 1);  // noise <= ~20 < 25 => safe cutoff
        }
    }
    if (tid == 0) g_prefix[T] = carryS;

    // block max-reduce for tcut
#pragma unroll
    for (int o = 16; o > 0; o >>= 1) tmax = max(tmax, __shfl_down_sync(0xffffffffu, tmax, o));
    if ((tid & 31) == 0) s_imax[tid >> 5] = tmax;
    __syncthreads();
    if (tid < 32) {
        int v = s_imax[tid];
#pragma unroll
        for (int o = 16; o > 0; o >>= 1) v = max(v, __shfl_down_sync(0xffffffffu, v, o));
        if (tid == 0) g_tcut = v;
    }
}

// Kernel 2: find first death step per lane.
// hard=1  <=>  sigmoid(logit+noise)>0.5  <=>  log(u2+e)/log(u1+e)+e < exp(logit)
//         <=>  log(u2+e) > (exp(logit)-e) * log(u1+e)       [log(u1+e) < 0]
__global__ void __launch_bounds__(256) k_scan(const float* __restrict__ u1,
                                              const float* __restrict__ u2,
                                              int T, int B) {
    int tstart = blockIdx.y * TCHUNK;
    if (tstart >= g_tcut) return;           // uniform: whole block exits

    __shared__ float s_T2[TCHUNK];
    if (threadIdx.x < TCHUNK) {
        int t = tstart + threadIdx.x;
        s_T2[threadIdx.x] = (t < T) ? g_T2[t] : -1.0f;
    }
    __syncthreads();

    int b = blockIdx.x * blockDim.x + threadIdx.x;
    if (b >= B) return;
    if (g_death[b] <= tstart) return;       // lane already dead before this chunk

    int tend = min(tstart + TCHUNK, T);
    const float EPSF = 1e-12f;
    for (int t = tstart; t < tend; t++) {
        float la = __logf(u2[(size_t)t * B + b] + EPSF);
        float lb = __logf(u1[(size_t)t * B + b] + EPSF);
        if (la > s_T2[t - tstart] * lb) {
            atomicMin(&g_death[b], t);
            break;
        }
    }
}

// Kernel 3: cumrew_lane = prefix[death], mean over lanes.
__global__ void __launch_bounds__(1024) k_reduce(float* __restrict__ out, int T, int B) {
    __shared__ double s_sum[32];
    double s = 0.0;
    for (int i = threadIdx.x; i < B; i += 1024) s += g_prefix[g_death[i]];
#pragma unroll
    for (int o = 16; o > 0; o >>= 1) s += __shfl_down_sync(0xffffffffu, s, o);
    if ((threadIdx.x & 31) == 0) s_sum[threadIdx.x >> 5] = s;
    __syncthreads();
    if (threadIdx.x < 32) {
        double v = s_sum[threadIdx.x];
#pragma unroll
        for (int o = 16; o > 0; o >>= 1) v += __shfl_down_sync(0xffffffffu, v, o);
        if (threadIdx.x == 0) out[0] = (float)(v / (double)B);
    }
}

extern "C" void kernel_launch(void* const* d_in, const int* in_sizes, int n_in,
                              void* d_out, int out_size) {
    const float* acts = (const float*)d_in[0];
    const float* u1   = (const float*)d_in[1];
    const float* u2   = (const float*)d_in[2];
    int T = in_sizes[0];
    int B = (T > 0) ? (in_sizes[1] / T) : 0;

    k_precompute<<<1, 1024>>>(acts, T, B);
    dim3 grid((B + 255) / 256, (T + TCHUNK - 1) / TCHUNK);
    k_scan<<<grid, 256>>>(u1, u2, T, B);
    k_reduce<<<1, 1024>>>((float*)d_out, T, B);
}

// round 3
// speedup vs baseline: 1.5000x; 1.5000x over previous
#include <cuda_runtime.h>
#include <math.h>
#include <stdint.h>

#define MAXT_C 10000
#define MAXB_C 4096
#define TCHUNK 64
#define NTH    1024
#define ELEMS  10        // ceil(10000/1024)

// Scratch (static __device__ arrays: no allocation allowed)
__device__ float   g_T2[MAXT_C];         // per-step death threshold: exp(logit_t) - eps
__device__ double  g_prefix[MAXT_C + 1]; // prefix[k] = sum_{t<k} w_t
__device__ int     g_death[MAXB_C];      // first death step per lane (T if none)
__device__ int     g_tcut;               // no deaths possible for t >= g_tcut

// Exclusive block-wide scan (blockDim.x == 1024), fp64.
__device__ __forceinline__ double block_scan_excl(double v, double& total, double* s_warp) {
    const unsigned FULL = 0xffffffffu;
    int lane = threadIdx.x & 31;
    int w    = threadIdx.x >> 5;
    double inc = v;
#pragma unroll
    for (int o = 1; o < 32; o <<= 1) {
        double n = __shfl_up_sync(FULL, inc, o);
        if (lane >= o) inc += n;
    }
    double exc = __shfl_up_sync(FULL, inc, 1);
    if (lane == 0) exc = 0.0;
    if (lane == 31) s_warp[w] = inc;
    __syncthreads();
    if (w == 0) {
        double i2 = s_warp[lane];
#pragma unroll
        for (int o = 1; o < 32; o <<= 1) {
            double n = __shfl_up_sync(FULL, i2, o);
            if (lane >= o) i2 += n;
        }
        double e2 = __shfl_up_sync(FULL, i2, 1);
        if (lane == 0) e2 = 0.0;
        s_warp[lane] = e2;
        if (lane == 31) s_warp[32] = i2;
    }
    __syncthreads();
    exc += s_warp[w];
    total = s_warp[32];
    __syncthreads();   // protect s_warp before next scan reuses it
    return exc;
}

// Kernel 1: scalar (batch-independent) precompute over T steps.
// Thread-coarsened: each thread owns ELEMS contiguous steps; only 3 block scans total.
__global__ void __launch_bounds__(NTH, 1) k_precompute(const float* __restrict__ acts, int T, int B) {
    __shared__ double s_warp[33];
    __shared__ int s_imax[32];
    int tid = threadIdx.x;
    int seg = tid * ELEMS;

    for (int i = tid; i < B; i += NTH) g_death[i] = T;

    const float LOG_GAMMA_F = (float)log(1.02);
    const float ALPHA_F     = (float)(log(0.99) / 1000.0);
    const float INIT_LOGW_F = (float)log(0.248);
    const float INIT_LOGP_F = (float)log(0.001);

    // ---- pass 1: c_j = LOG_GAMMA + log(1 - exp(a_j)), local sum ----
    float cArr[ELEMS];
    double csum = 0.0;
#pragma unroll
    for (int j = 0; j < ELEMS; j++) {
        int i = seg + j;
        float c = 0.0f;
        if (i < T) {
            float f = expf(acts[i]);
            c = LOG_GAMMA_F + logf(1.0f - f);
        }
        cArr[j] = c;
        csum += (double)c;
    }
    double tot;
    double Wbase = block_scan_excl(csum, tot, s_warp) + (double)INIT_LOGW_F;

    // ---- pass 2: df_j = ALPHA * f_j * exp(W_j), local sum (W_j = logw entering step j) ----
    double dfsum = 0.0;
    {
        double W = Wbase;
#pragma unroll
        for (int j = 0; j < ELEMS; j++) {
            int i = seg + j;
            if (i < T) {
                float Wf = (float)W;
                float f  = expf(acts[i]);
                dfsum += (double)(ALPHA_F * f * expf(Wf));
            }
            W += (double)cArr[j];
        }
    }
    double Pbase = block_scan_excl(dfsum, tot, s_warp) + (double)INIT_LOGP_F;

    // ---- pass 3: threshold from logit(P_j); reward wv_j = exp((W_j + c_j)/1000); tcut ----
    double wvsum = 0.0;
    int tmax = 0;
    {
        double W = Wbase, P = Pbase;
#pragma unroll
        for (int j = 0; j < ELEMS; j++) {
            int i = seg + j;
            if (i < T) {
                float Wf = (float)W;
                float Pf = (float)P;
                float logit = Pf - log1pf(-expf(Pf));
                float thr = expf(logit);
                g_T2[i] = thr - 1e-12f;
                if (logit >= -25.0f) tmax = max(tmax, i + 1);   // noise <= ~20 < 25 => safe cutoff
                wvsum += (double)expf((Wf + cArr[j]) / 1000.0f);
                float f = expf(acts[i]);
                P += (double)(ALPHA_F * f * expf(Wf));
            }
            W += (double)cArr[j];
        }
    }
    double Sbase = block_scan_excl(wvsum, tot, s_warp);

    // ---- pass 4: write exclusive reward prefix ----
    {
        double W = Wbase, S = Sbase;
#pragma unroll
        for (int j = 0; j < ELEMS; j++) {
            int i = seg + j;
            if (i < T) {
                g_prefix[i] = S;
                S += (double)expf(((float)W + cArr[j]) / 1000.0f);
            }
            W += (double)cArr[j];
        }
    }
    if (tid == 0) g_prefix[T] = tot;   // total reward sum

    // block max-reduce for tcut
#pragma unroll
    for (int o = 16; o > 0; o >>= 1) tmax = max(tmax, __shfl_down_sync(0xffffffffu, tmax, o));
    if ((tid & 31) == 0) s_imax[tid >> 5] = tmax;
    __syncthreads();
    if (tid < 32) {
        int v = s_imax[tid];
#pragma unroll
        for (int o = 16; o > 0; o >>= 1) v = max(v, __shfl_down_sync(0xffffffffu, v, o));
        if (tid == 0) g_tcut = v;
    }
}

// Kernel 2: find first death step per lane.
// hard=1  <=>  log(u2+e) > (exp(logit)-e) * log(u1+e)   [log(u1+e) < 0]
__global__ void __launch_bounds__(256) k_scan(const float* __restrict__ u1,
                                              const float* __restrict__ u2,
                                              int T, int B) {
    int tstart = blockIdx.y * TCHUNK;
    if (tstart >= g_tcut) return;           // uniform: whole block exits

    __shared__ float s_T2[TCHUNK];
    if (threadIdx.x < TCHUNK) {
        int t = tstart + threadIdx.x;
        s_T2[threadIdx.x] = (t < T) ? g_T2[t] : -1.0f;
    }
    __syncthreads();

    int b = blockIdx.x * blockDim.x + threadIdx.x;
    if (b >= B) return;
    if (g_death[b] <= tstart) return;       // lane already dead before this chunk

    int tend = min(tstart + TCHUNK, T);
    const float EPSF = 1e-12f;
    for (int t = tstart; t < tend; t++) {
        float la = __logf(u2[(size_t)t * B + b] + EPSF);
        float lb = __logf(u1[(size_t)t * B + b] + EPSF);
        if (la > s_T2[t - tstart] * lb) {
            atomicMin(&g_death[b], t);
            break;
        }
    }
}

// Kernel 3: cumrew_lane = prefix[death], mean over lanes.
__global__ void __launch_bounds__(1024) k_reduce(float* __restrict__ out, int T, int B) {
    __shared__ double s_sum[32];
    double s = 0.0;
    for (int i = threadIdx.x; i < B; i += 1024) s += g_prefix[g_death[i]];
#pragma unroll
    for (int o = 16; o > 0; o >>= 1) s += __shfl_down_sync(0xffffffffu, s, o);
    if ((threadIdx.x & 31) == 0) s_sum[threadIdx.x >> 5] = s;
    __syncthreads();
    if (threadIdx.x < 32) {
        double v = s_sum[threadIdx.x];
#pragma unroll
        for (int o = 16; o > 0; o >>= 1) v += __shfl_down_sync(0xffffffffu, v, o);
        if (threadIdx.x == 0) out[0] = (float)(v / (double)B);
    }
}

extern "C" void kernel_launch(void* const* d_in, const int* in_sizes, int n_in,
                              void* d_out, int out_size) {
    const float* acts = (const float*)d_in[0];
    const float* u1   = (const float*)d_in[1];
    const float* u2   = (const float*)d_in[2];
    int T = in_sizes[0];
    int B = (T > 0) ? (in_sizes[1] / T) : 0;

    k_precompute<<<1, NTH>>>(acts, T, B);
    dim3 grid((B + 255) / 256, (T + TCHUNK - 1) / TCHUNK);
    k_scan<<<grid, 256>>>(u1, u2, T, B);
    k_reduce<<<1, 1024>>>((float*)d_out, T, B);
}

// round 4
// speedup vs baseline: 2.0490x; 1.3660x over previous
#include <cuda_runtime.h>
#include <math.h>
#include <stdint.h>

#define MAXT_C 10000
#define MAXB_C 4096
#define TCHUNK 64
#define NTH    1024
#define ELEMS  10        // ceil(10000/1024)

// Scratch (static __device__ arrays: no allocation allowed)
__device__ float   g_T2[MAXT_C];         // per-step death threshold: exp(logit_t) - eps
__device__ double  g_prefix[MAXT_C + 1]; // prefix[k] = sum_{t<k} w_t
__device__ int     g_death[MAXB_C];      // first death step per lane (T if none)
__device__ int     g_tcut;               // no deaths possible for t >= g_tcut
__device__ int     g_done;               // block completion counter for fused reduce

// Exclusive block-wide scan (blockDim.x == 1024), fp64.
__device__ __forceinline__ double block_scan_excl(double v, double& total, double* s_warp) {
    const unsigned FULL = 0xffffffffu;
    int lane = threadIdx.x & 31;
    int w    = threadIdx.x >> 5;
    double inc = v;
#pragma unroll
    for (int o = 1; o < 32; o <<= 1) {
        double n = __shfl_up_sync(FULL, inc, o);
        if (lane >= o) inc += n;
    }
    double exc = __shfl_up_sync(FULL, inc, 1);
    if (lane == 0) exc = 0.0;
    if (lane == 31) s_warp[w] = inc;
    __syncthreads();
    if (w == 0) {
        double i2 = s_warp[lane];
#pragma unroll
        for (int o = 1; o < 32; o <<= 1) {
            double n = __shfl_up_sync(FULL, i2, o);
            if (lane >= o) i2 += n;
        }
        double e2 = __shfl_up_sync(FULL, i2, 1);
        if (lane == 0) e2 = 0.0;
        s_warp[lane] = e2;
        if (lane == 31) s_warp[32] = i2;
    }
    __syncthreads();
    exc += s_warp[w];
    total = s_warp[32];
    __syncthreads();   // protect s_warp before next scan reuses it
    return exc;
}

// Kernel 1: scalar (batch-independent) precompute over T steps.
// Thread-coarsened (ELEMS steps/thread). fp64 only between threads (3 block
// scans); all intra-thread chains are fp32 (FADD lat 4). MUFU transcendentals.
__global__ void __launch_bounds__(NTH, 1) k_precompute(const float* __restrict__ acts, int T, int B) {
    __shared__ double s_warp[33];
    __shared__ int s_imax[32];
    int tid = threadIdx.x;
    int seg = tid * ELEMS;

    for (int i = tid; i < B; i += NTH) g_death[i] = T;
    if (tid == 0) g_done = 0;

    const float LOG_GAMMA_F = (float)log(1.02);
    const float ALPHA_F     = (float)(log(0.99) / 1000.0);
    const float INIT_LOGW_F = (float)log(0.248);
    const float INIT_LOGP_F = (float)log(0.001);

    // ---- pass 1: f_j = exp(a_j); c_j = LOG_GAMMA + log(1 - f_j); local fp32 sum ----
    float fArr[ELEMS], cArr[ELEMS];
    float csum = 0.0f;
#pragma unroll
    for (int j = 0; j < ELEMS; j++) {
        int i = seg + j;
        float f = 0.0f, c = 0.0f;
        if (i < T) {
            f = __expf(acts[i]);
            c = LOG_GAMMA_F + __logf(1.0f - f);
        }
        fArr[j] = f;
        cArr[j] = c;
        csum += c;
    }
    double tot;
    double Wbase_d = block_scan_excl((double)csum, tot, s_warp) + (double)INIT_LOGW_F;
    float  Wbase   = (float)Wbase_d;

    // ---- pass 2: df_j = ALPHA * f_j * exp(W_j), local fp32 sum ----
    float dfsum = 0.0f;
    {
        float lw = 0.0f;
#pragma unroll
        for (int j = 0; j < ELEMS; j++) {
            int i = seg + j;
            if (i < T)
                dfsum += ALPHA_F * fArr[j] * __expf(Wbase + lw);
            lw += cArr[j];
        }
    }
    double Pbase_d = block_scan_excl((double)dfsum, tot, s_warp) + (double)INIT_LOGP_F;
    float  Pbase   = (float)Pbase_d;

    // ---- pass 3: thr_j = q/(1-q), q = exp(P_j); reward wv_j = exp((W_j+c_j)/1000) ----
    float wvArr[ELEMS];
    float wvsum = 0.0f;
    int tmax = 0;
    {
        float lw = 0.0f, lp = 0.0f;
#pragma unroll
        for (int j = 0; j < ELEMS; j++) {
            int i = seg + j;
            float wv = 0.0f;
            if (i < T) {
                float Wf = Wbase + lw;
                float q  = __expf(Pbase + lp);
                float thr = __fdividef(q, 1.0f - q);     // = exp(logit)
                g_T2[i] = thr - 1e-12f;
                if (q >= 1.4e-11f) tmax = max(tmax, i + 1);  // logit >= -25 (noise <= ~20)
                wv = __expf((Wf + cArr[j]) * 0.001f);
                lp += ALPHA_F * fArr[j] * __expf(Wf);
            }
            wvArr[j] = wv;
            wvsum += wv;
            lw += cArr[j];
        }
    }
    double Sbase = block_scan_excl((double)wvsum, tot, s_warp);

    // ---- pass 4: exclusive reward prefix: fp64 base + fp32 local prefix ----
    {
        float ls = 0.0f;
#pragma unroll
        for (int j = 0; j < ELEMS; j++) {
            int i = seg + j;
            if (i < T) g_prefix[i] = Sbase + (double)ls;
            ls += wvArr[j];
        }
    }
    if (tid == 0) g_prefix[T] = tot;   // total reward sum

    // block max-reduce for tcut
#pragma unroll
    for (int o = 16; o > 0; o >>= 1) tmax = max(tmax, __shfl_down_sync(0xffffffffu, tmax, o));
    if ((tid & 31) == 0) s_imax[tid >> 5] = tmax;
    __syncthreads();
    if (tid < 32) {
        int v = s_imax[tid];
#pragma unroll
        for (int o = 16; o > 0; o >>= 1) v = max(v, __shfl_down_sync(0xffffffffu, v, o));
        if (tid == 0) g_tcut = v;
    }
}

// Kernel 2: find first death step per lane, then the LAST block to finish
// performs the mean-reduction (fused k_reduce).
// hard=1  <=>  log(u2+e) > (exp(logit)-e) * log(u1+e)   [log(u1+e) < 0]
__global__ void __launch_bounds__(256) k_scan(const float* __restrict__ u1,
                                              const float* __restrict__ u2,
                                              float* __restrict__ out,
                                              int T, int B, int nblocks) {
    int tstart = blockIdx.y * TCHUNK;
    __shared__ float s_T2[TCHUNK];
    bool active = (tstart < g_tcut);          // uniform per block
    if (active) {
        if (threadIdx.x < TCHUNK) {
            int t = tstart + threadIdx.x;
            s_T2[threadIdx.x] = (t < T) ? g_T2[t] : -1.0f;
        }
        __syncthreads();
        int b = blockIdx.x * blockDim.x + threadIdx.x;
        if (b < B && g_death[b] > tstart) {
            int tend = min(tstart + TCHUNK, T);
            const float EPSF = 1e-12f;
            for (int t = tstart; t < tend; t++) {
                float la = __logf(u2[(size_t)t * B + b] + EPSF);
                float lb = __logf(u1[(size_t)t * B + b] + EPSF);
                if (la > s_T2[t - tstart] * lb) {
                    atomicMin(&g_death[b], t);
                    break;
                }
            }
        }
        __syncthreads();
    }

    // ---- completion protocol: last block reduces ----
    __threadfence();
    __shared__ int lastFlag;
    if (threadIdx.x == 0)
        lastFlag = (atomicAdd(&g_done, 1) == nblocks - 1);
    __syncthreads();
    if (!lastFlag) return;

    __shared__ double s_red[8];
    double s = 0.0;
    for (int i = threadIdx.x; i < B; i += 256) s += g_prefix[g_death[i]];
#pragma unroll
    for (int o = 16; o > 0; o >>= 1) s += __shfl_down_sync(0xffffffffu, s, o);
    if ((threadIdx.x & 31) == 0) s_red[threadIdx.x >> 5] = s;
    __syncthreads();
    if (threadIdx.x < 8) {
        double v = s_red[threadIdx.x];
#pragma unroll
        for (int o = 4; o > 0; o >>= 1) v += __shfl_down_sync(0xffu, v, o);
        if (threadIdx.x == 0) out[0] = (float)(v / (double)B);
    }
}

extern "C" void kernel_launch(void* const* d_in, const int* in_sizes, int n_in,
                              void* d_out, int out_size) {
    const float* acts = (const float*)d_in[0];
    const float* u1   = (const float*)d_in[1];
    const float* u2   = (const float*)d_in[2];
    int T = in_sizes[0];
    int B = (T > 0) ? (in_sizes[1] / T) : 0;

    k_precompute<<<1, NTH>>>(acts, T, B);
    dim3 grid((B + 255) / 256, (T + TCHUNK - 1) / TCHUNK);
    k_scan<<<grid, 256>>>(u1, u2, (float*)d_out, T, B, (int)(grid.x * grid.y));
}

// round 5
// speedup vs baseline: 2.8630x; 1.3973x over previous
#include <cuda_runtime.h>
#include <math.h>
#include <stdint.h>

#define MAXT_C 10000
#define MAXB_C 4096
#define TCHUNK 32
#define NTH    512
#define ELEMS  20        // ceil(10000/512)
#define NCHUNK ((MAXT_C + TCHUNK - 1) / TCHUNK)

// Scratch (static __device__ arrays: no allocation allowed)
__device__ float   g_f[MAXT_C];          // exp(acts[t])
__device__ float   g_c[MAXT_C];          // LOG_GAMMA + log(1 - f)
__device__ float   g_T2[MAXT_C];         // per-step death threshold: exp(logit_t) - eps
__device__ float   g_u2min[NCHUNK];      // per-chunk screen: death impossible unless u2 > this
__device__ double  g_prefix[MAXT_C + 1]; // prefix[k] = sum_{t<k} w_t
__device__ int     g_death[MAXB_C];      // first death step per lane (T if none)
__device__ int     g_tcut;               // no deaths possible for t >= g_tcut
__device__ int     g_done;               // block completion counter for fused reduce

// ---------------------------------------------------------------------------
// Kernel P1: wide-parallel elementwise transcendentals + init.
__global__ void __launch_bounds__(512) k_elemwise(const float* __restrict__ acts, int T, int B) {
    const float LOG_GAMMA_F = (float)log(1.02);
    int i = blockIdx.x * 512 + threadIdx.x;
    if (i < T) {
        float f = __expf(acts[i]);
        g_f[i] = f;
        g_c[i] = LOG_GAMMA_F + __logf(1.0f - f);
    }
    if (i < B) g_death[i] = T;
    if (i == 0) g_done = 0;
}

// ---------------------------------------------------------------------------
// Exclusive block-wide scan (blockDim.x == NTH), fp64.
__device__ __forceinline__ double block_scan_excl(double v, double& total, double* s_warp) {
    const unsigned FULL = 0xffffffffu;
    int lane = threadIdx.x & 31;
    int w    = threadIdx.x >> 5;
    const int NW = NTH / 32;
    double inc = v;
#pragma unroll
    for (int o = 1; o < 32; o <<= 1) {
        double n = __shfl_up_sync(FULL, inc, o);
        if (lane >= o) inc += n;
    }
    double exc = __shfl_up_sync(FULL, inc, 1);
    if (lane == 0) exc = 0.0;
    if (lane == 31) s_warp[w] = inc;
    __syncthreads();
    if (w == 0 && lane < NW) {
        double i2 = s_warp[lane];
#pragma unroll
        for (int o = 1; o < NW; o <<= 1) {
            double n = __shfl_up_sync((1u << NW) - 1u, i2, o);
            if (lane >= o) i2 += n;
        }
        double e2 = __shfl_up_sync((1u << NW) - 1u, i2, 1);
        if (lane == 0) e2 = 0.0;
        s_warp[lane] = e2;
        if (lane == NW - 1) s_warp[NW] = i2;
    }
    __syncthreads();
    exc += s_warp[w];
    total = s_warp[NW];
    __syncthreads();
    return exc;
}

// ---------------------------------------------------------------------------
// Kernel B: single-block scan over T. Per-element MUFU minimized:
// e^{W} via multiplicative chain (e^{W+c} = e^{W} * 1.02*(1-f)); only
// exp(P), one divide, and exp(wv) remain per element.
__global__ void __launch_bounds__(NTH, 1) k_precompute(int T, int B) {
    __shared__ double s_warp[NTH / 32 + 1];
    __shared__ int s_imax[NTH / 32];
    int tid = threadIdx.x;
    int seg = tid * ELEMS;

    const float ALPHA_F     = (float)(log(0.99) / 1000.0);
    const float INIT_LOGW_F = (float)log(0.248);
    const float INIT_LOGP_F = (float)log(0.001);

    // ---- pass 1: load f, c; local c-sum; scan -> Wbase ----
    float fArr[ELEMS], cArr[ELEMS];
    float csum = 0.0f;
#pragma unroll
    for (int j = 0; j < ELEMS; j++) {
        int i = seg + j;
        float f = 0.0f, c = 0.0f;
        if (i < T) { f = g_f[i]; c = g_c[i]; }
        fArr[j] = f; cArr[j] = c;
        csum += c;
    }
    double tot;
    double Wbase_d = block_scan_excl((double)csum, tot, s_warp) + (double)INIT_LOGW_F;
    float  Wbase   = (float)Wbase_d;

    // ---- pass 2: df_j = ALPHA * f_j * e^{W_j}; e^{W} multiplicative chain ----
    float dfsum = 0.0f;
    {
        float ew = __expf(Wbase);           // one MUFU per thread
#pragma unroll
        for (int j = 0; j < ELEMS; j++) {
            int i = seg + j;
            if (i < T) {
                dfsum += ALPHA_F * fArr[j] * ew;
                ew *= 1.02f * (1.0f - fArr[j]);   // = ew * e^{c_j}
            }
        }
    }
    double Pbase_d = block_scan_excl((double)dfsum, tot, s_warp) + (double)INIT_LOGP_F;
    float  Pbase   = (float)Pbase_d;

    // ---- pass 3: thresholds, per-chunk screen consts, rewards ----
    float wvArr[ELEMS];
    float wvsum = 0.0f;
    int tmax = 0;
    {
        float lw = 0.0f, lp = 0.0f;
        float ew = __expf(Wbase);
#pragma unroll
        for (int j = 0; j < ELEMS; j++) {
            int i = seg + j;
            float wv = 0.0f;
            if (i < T) {
                float Wf = Wbase + lw;
                float q  = __expf(Pbase + lp);
                float thr = __fdividef(q, 1.0f - q);       // = exp(logit)
                float T2  = thr - 1e-12f;
                g_T2[i] = T2;
                if ((i & (TCHUNK - 1)) == 0)               // chunk screen (T2 monotone dec.)
                    g_u2min[i / TCHUNK] = __expf(-27.64f * T2) * (1.0f - 1e-5f);
                if (q >= 1.4e-11f) tmax = max(tmax, i + 1); // logit >= -25 (noise <= ~20)
                wv = __expf((Wf + cArr[j]) * 0.001f);
                lp += ALPHA_F * fArr[j] * ew;
                ew *= 1.02f * (1.0f - fArr[j]);
                lw += cArr[j];
            }
            wvArr[j] = wv;
            wvsum += wv;
        }
    }
    double Sbase = block_scan_excl((double)wvsum, tot, s_warp);

    // ---- pass 4: exclusive reward prefix ----
    {
        float ls = 0.0f;
#pragma unroll
        for (int j = 0; j < ELEMS; j++) {
            int i = seg + j;
            if (i < T) g_prefix[i] = Sbase + (double)ls;
            ls += wvArr[j];
        }
    }
    if (tid == 0) g_prefix[T] = tot;

    // ---- block max-reduce for tcut ----
#pragma unroll
    for (int o = 16; o > 0; o >>= 1) tmax = max(tmax, __shfl_down_sync(0xffffffffu, tmax, o));
    if ((tid & 31) == 0) s_imax[tid >> 5] = tmax;
    __syncthreads();
    if (tid < NTH / 32) {
        int v = s_imax[tid];
#pragma unroll
        for (int o = (NTH / 64); o > 0; o >>= 1)
            v = max(v, __shfl_down_sync((1u << (NTH / 32)) - 1u, v, o));
        if (tid == 0) g_tcut = v;
    }
}

// ---------------------------------------------------------------------------
// Kernel C: screened death scan (vec4 over lanes) + fused final reduce.
// Screen: death at (t,b) impossible unless u2 > g_u2min[chunk] (~2.7% pass),
// so the expensive 2x log test runs only on rare candidates, and u1 is only
// ever loaded for candidates.
__global__ void __launch_bounds__(256) k_scan(const float* __restrict__ u1,
                                              const float* __restrict__ u2,
                                              float* __restrict__ out,
                                              int T, int B, int nblocks) {
    int tstart = blockIdx.y * TCHUNK;
    __shared__ float s_T2[TCHUNK];
    bool active = (tstart < g_tcut);          // uniform per block
    if (active) {
        if (threadIdx.x < TCHUNK) {
            int t = tstart + threadIdx.x;
            s_T2[threadIdx.x] = (t < T) ? g_T2[t] : -1.0f;
        }
        __syncthreads();
        float u2min = g_u2min[blockIdx.y];
        int b4 = (blockIdx.x * blockDim.x + threadIdx.x) * 4;
        if (b4 + 3 < B) {
            const float4* u2v = (const float4*)u2;
            int tend = min(TCHUNK, T - tstart);
            unsigned m0 = 0, m1 = 0, m2 = 0, m3 = 0;
#pragma unroll
            for (int t = 0; t < TCHUNK; t++) {
                if (t < tend) {
                    float4 v = u2v[((size_t)(tstart + t) * B + b4) >> 2];
                    if (v.x > u2min) m0 |= 1u << t;
                    if (v.y > u2min) m1 |= 1u << t;
                    if (v.z > u2min) m2 |= 1u << t;
                    if (v.w > u2min) m3 |= 1u << t;
                }
            }
            const float EPSF = 1e-12f;
#pragma unroll
            for (int l = 0; l < 4; l++) {
                unsigned m = (l == 0) ? m0 : (l == 1) ? m1 : (l == 2) ? m2 : m3;
                while (m) {
                    int t = __ffs(m) - 1;
                    m &= m - 1;
                    size_t idx = (size_t)(tstart + t) * B + b4 + l;
                    float la = __logf(u2[idx] + EPSF);
                    float lb = __logf(u1[idx] + EPSF);
                    if (la > s_T2[t] * lb) {
                        atomicMin(&g_death[b4 + l], tstart + t);
                        break;              // bits ascend in t: first hit = chunk minimum
                    }
                }
            }
        }
        __syncthreads();
    }

    // ---- completion protocol: last block reduces ----
    __threadfence();
    __shared__ int lastFlag;
    if (threadIdx.x == 0)
        lastFlag = (atomicAdd(&g_done, 1) == nblocks - 1);
    __syncthreads();
    if (!lastFlag) return;

    __shared__ double s_red[8];
    double s = 0.0;
    for (int i = threadIdx.x; i < B; i += 256) s += g_prefix[g_death[i]];
#pragma unroll
    for (int o = 16; o > 0; o >>= 1) s += __shfl_down_sync(0xffffffffu, s, o);
    if ((threadIdx.x & 31) == 0) s_red[threadIdx.x >> 5] = s;
    __syncthreads();
    if (threadIdx.x < 8) {
        double v = s_red[threadIdx.x];
#pragma unroll
        for (int o = 4; o > 0; o >>= 1) v += __shfl_down_sync(0xffu, v, o);
        if (threadIdx.x == 0) out[0] = (float)(v / (double)B);
    }
}

extern "C" void kernel_launch(void* const* d_in, const int* in_sizes, int n_in,
                              void* d_out, int out_size) {
    const float* acts = (const float*)d_in[0];
    const float* u1   = (const float*)d_in[1];
    const float* u2   = (const float*)d_in[2];
    int T = in_sizes[0];
    int B = (T > 0) ? (in_sizes[1] / T) : 0;

    int initN = (T > B) ? T : B;
    k_elemwise<<<(initN + 511) / 512, 512>>>(acts, T, B);
    k_precompute<<<1, NTH>>>(T, B);
    dim3 grid((B + 1023) / 1024, (T + TCHUNK - 1) / TCHUNK);
    k_scan<<<grid, 256>>>(u1, u2, (float*)d_out, T, B, (int)(grid.x * grid.y));
}

// round 6
// speedup vs baseline: 2.9893x; 1.0441x over previous
#include <cuda_runtime.h>
#include <math.h>
#include <stdint.h>

#define MAXT_C 10000
#define MAXB_C 4096
#define TCHUNK 16
#define NTH    512
#define ELEMS  20        // ceil(10000/512)
#define NCHUNK ((MAXT_C + TCHUNK - 1) / TCHUNK)

// Scratch (static __device__ arrays: no allocation allowed)
__device__ float   g_f[MAXT_C];          // exp(acts[t])
__device__ float   g_c[MAXT_C];          // LOG_GAMMA + log(1 - f)
__device__ float   g_T2[MAXT_C];         // per-step death threshold: exp(logit_t) - eps
__device__ float   g_wv[MAXT_C];         // per-step reward weight exp(new_logw/1000)
__device__ float   g_u2min[NCHUNK];      // per-chunk screen: death impossible unless u2 > this
__device__ double  g_Wbase[NTH];         // per-segment logw base (incl. INIT_LOGW)
__device__ double  g_Pbase[NTH];         // per-segment logp base (incl. INIT_LOGP)
__device__ double  g_prefix[MAXT_C + 1]; // prefix[k] = sum_{t<k} w_t
__device__ int     g_death[MAXB_C];      // first death step per lane (T if none)
__device__ int     g_tcut;               // no deaths possible for t >= g_tcut
__device__ int     g_done;               // block completion counter for fused reduce

// ---------------------------------------------------------------------------
// K1: wide elementwise transcendentals + state init.
__global__ void __launch_bounds__(512) k_elemwise(const float* __restrict__ acts, int T, int B) {
    const float LOG_GAMMA_F = (float)log(1.02);
    int i = blockIdx.x * 512 + threadIdx.x;
    if (i < T) {
        float f = __expf(acts[i]);
        g_f[i] = f;
        g_c[i] = LOG_GAMMA_F + __logf(1.0f - f);
    }
    if (i < B) g_death[i] = T;
    if (i == 0) { g_done = 0; g_tcut = 0; }
}

// ---------------------------------------------------------------------------
// Exclusive block-wide scan (blockDim.x == NTH), fp64.
__device__ __forceinline__ double block_scan_excl(double v, double& total, double* s_warp) {
    const unsigned FULL = 0xffffffffu;
    int lane = threadIdx.x & 31;
    int w    = threadIdx.x >> 5;
    const int NW = NTH / 32;
    double inc = v;
#pragma unroll
    for (int o = 1; o < 32; o <<= 1) {
        double n = __shfl_up_sync(FULL, inc, o);
        if (lane >= o) inc += n;
    }
    double exc = __shfl_up_sync(FULL, inc, 1);
    if (lane == 0) exc = 0.0;
    if (lane == 31) s_warp[w] = inc;
    __syncthreads();
    if (w == 0 && lane < NW) {
        double i2 = s_warp[lane];
#pragma unroll
        for (int o = 1; o < NW; o <<= 1) {
            double n = __shfl_up_sync((1u << NW) - 1u, i2, o);
            if (lane >= o) i2 += n;
        }
        double e2 = __shfl_up_sync((1u << NW) - 1u, i2, 1);
        if (lane == 0) e2 = 0.0;
        s_warp[lane] = e2;
        if (lane == NW - 1) s_warp[NW] = i2;
    }
    __syncthreads();
    exc += s_warp[w];
    total = s_warp[NW];
    __syncthreads();
    return exc;
}

// ---------------------------------------------------------------------------
// K2: single-block, scan-only. Two fp64 block scans over per-segment sums.
// Per-element work is just FMULs (e^W multiplicative chain); one __expf/thread.
__global__ void __launch_bounds__(NTH, 1) k_scanbases(int T) {
    __shared__ double s_warp[NTH / 32 + 1];
    int tid = threadIdx.x;
    int seg = tid * ELEMS;

    const float ALPHA_F     = (float)(log(0.99) / 1000.0);
    const float INIT_LOGW_F = (float)log(0.248);
    const float INIT_LOGP_F = (float)log(0.001);

    float fArr[ELEMS], cArr[ELEMS];
    float csum = 0.0f;
#pragma unroll
    for (int j = 0; j < ELEMS; j++) {
        int i = seg + j;
        float f = 0.0f, c = 0.0f;
        if (i < T) { f = g_f[i]; c = g_c[i]; }
        fArr[j] = f; cArr[j] = c;
        csum += c;
    }
    double tot;
    double Wbase_d = block_scan_excl((double)csum, tot, s_warp) + (double)INIT_LOGW_F;
    g_Wbase[tid] = Wbase_d;

    float dfsum = 0.0f;
    {
        float ew = __expf((float)Wbase_d);
#pragma unroll
        for (int j = 0; j < ELEMS; j++) {
            int i = seg + j;
            if (i < T) {
                dfsum += ALPHA_F * fArr[j] * ew;
                ew *= 1.02f * (1.0f - fArr[j]);   // = ew * e^{c_j}
            }
        }
    }
    double Pbase_d = block_scan_excl((double)dfsum, tot, s_warp) + (double)INIT_LOGP_F;
    g_Pbase[tid] = Pbase_d;
}

// ---------------------------------------------------------------------------
// K3: wide elementwise heavy-MUFU pass. 512 segment-walkers over 16 SMs.
__global__ void __launch_bounds__(32) k_thresholds(int T) {
    int s = blockIdx.x * 32 + threadIdx.x;
    int seg = s * ELEMS;
    const float ALPHA_F = (float)(log(0.99) / 1000.0);

    float Wbase = (float)g_Wbase[s];
    float Pbase = (float)g_Pbase[s];
    float ew = __expf(Wbase);
    float lw = 0.0f, lp = 0.0f;
    int tmax = 0;
#pragma unroll
    for (int j = 0; j < ELEMS; j++) {
        int i = seg + j;
        if (i < T) {
            float f = g_f[i], c = g_c[i];
            float q = __expf(Pbase + lp);
            float thr = __fdividef(q, 1.0f - q);        // = exp(logit)
            float T2  = thr - 1e-12f;
            g_T2[i] = T2;
            if ((i & (TCHUNK - 1)) == 0)                 // T2 monotone decreasing in t
                g_u2min[i / TCHUNK] = __expf(-27.64f * T2) * (1.0f - 1e-5f);
            if (q >= 1.4e-11f) tmax = i + 1;             // logit >= -25 (noise <= ~20)
            g_wv[i] = __expf((Wbase + lw + c) * 0.001f);
            lp += ALPHA_F * f * ew;
            ew *= 1.02f * (1.0f - f);
            lw += c;
        }
    }
#pragma unroll
    for (int o = 16; o > 0; o >>= 1) tmax = max(tmax, __shfl_down_sync(0xffffffffu, tmax, o));
    if (threadIdx.x == 0 && tmax > 0) atomicMax(&g_tcut, tmax);
}

// ---------------------------------------------------------------------------
// K4: single-block MUFU-free prefix scan of wv -> g_prefix.
__global__ void __launch_bounds__(NTH, 1) k_wvprefix(int T) {
    __shared__ double s_warp[NTH / 32 + 1];
    int tid = threadIdx.x;
    int seg = tid * ELEMS;

    float wvArr[ELEMS];
    float wvsum = 0.0f;
#pragma unroll
    for (int j = 0; j < ELEMS; j++) {
        int i = seg + j;
        float wv = (i < T) ? g_wv[i] : 0.0f;
        wvArr[j] = wv;
        wvsum += wv;
    }
    double tot;
    double Sbase = block_scan_excl((double)wvsum, tot, s_warp);
    float ls = 0.0f;
#pragma unroll
    for (int j = 0; j < ELEMS; j++) {
        int i = seg + j;
        if (i < T) g_prefix[i] = Sbase + (double)ls;
        ls += wvArr[j];
    }
    if (tid == 0) g_prefix[T] = tot;
}

// ---------------------------------------------------------------------------
// K5: screened death scan (vec4 over lanes) + fused final reduce.
// Death at (t,b) impossible unless u2 > g_u2min[chunk]; slow path (2x log,
// u1 load) only for the rare candidates.
__global__ void __launch_bounds__(256) k_scan(const float* __restrict__ u1,
                                              const float* __restrict__ u2,
                                              float* __restrict__ out,
                                              int T, int B, int nblocks) {
    int tstart = blockIdx.y * TCHUNK;
    __shared__ float s_T2[TCHUNK];
    bool active = (tstart < g_tcut);          // uniform per block
    if (active) {
        if (threadIdx.x < TCHUNK) {
            int t = tstart + threadIdx.x;
            s_T2[threadIdx.x] = (t < T) ? g_T2[t] : -1.0f;
        }
        __syncthreads();
        float u2min = g_u2min[blockIdx.y];
        int b4 = (blockIdx.x * blockDim.x + threadIdx.x) * 4;
        if (b4 + 3 < B) {
            const float4* u2v = (const float4*)u2;
            int tend = min(TCHUNK, T - tstart);
            unsigned m0 = 0, m1 = 0, m2 = 0, m3 = 0;
#pragma unroll
            for (int t = 0; t < TCHUNK; t++) {
                if (t < tend) {
                    float4 v = u2v[((size_t)(tstart + t) * B + b4) >> 2];
                    if (v.x > u2min) m0 |= 1u << t;
                    if (v.y > u2min) m1 |= 1u << t;
                    if (v.z > u2min) m2 |= 1u << t;
                    if (v.w > u2min) m3 |= 1u << t;
                }
            }
            const float EPSF = 1e-12f;
#pragma unroll
            for (int l = 0; l < 4; l++) {
                unsigned m = (l == 0) ? m0 : (l == 1) ? m1 : (l == 2) ? m2 : m3;
                while (m) {
                    int t = __ffs(m) - 1;
                    m &= m - 1;
                    size_t idx = (size_t)(tstart + t) * B + b4 + l;
                    float la = __logf(u2[idx] + EPSF);
                    float lb = __logf(u1[idx] + EPSF);
                    if (la > s_T2[t] * lb) {
                        atomicMin(&g_death[b4 + l], tstart + t);
                        break;              // bits ascend in t: first hit = chunk minimum
                    }
                }
            }
        }
        __syncthreads();
    }

    // ---- completion protocol: last block reduces ----
    __threadfence();
    __shared__ int lastFlag;
    if (threadIdx.x == 0)
        lastFlag = (atomicAdd(&g_done, 1) == nblocks - 1);
    __syncthreads();
    if (!lastFlag) return;

    __shared__ double s_red[8];
    double s = 0.0;
    for (int i = threadIdx.x; i < B; i += 256) s += g_prefix[g_death[i]];
#pragma unroll
    for (int o = 16; o > 0; o >>= 1) s += __shfl_down_sync(0xffffffffu, s, o);
    if ((threadIdx.x & 31) == 0) s_red[threadIdx.x >> 5] = s;
    __syncthreads();
    if (threadIdx.x < 8) {
        double v = s_red[threadIdx.x];
#pragma unroll
        for (int o = 4; o > 0; o >>= 1) v += __shfl_down_sync(0xffu, v, o);
        if (threadIdx.x == 0) out[0] = (float)(v / (double)B);
    }
}

extern "C" void kernel_launch(void* const* d_in, const int* in_sizes, int n_in,
                              void* d_out, int out_size) {
    const float* acts = (const float*)d_in[0];
    const float* u1   = (const float*)d_in[1];
    const float* u2   = (const float*)d_in[2];
    int T = in_sizes[0];
    int B = (T > 0) ? (in_sizes[1] / T) : 0;

    int initN = (T > B) ? T : B;
    k_elemwise<<<(initN + 511) / 512, 512>>>(acts, T, B);
    k_scanbases<<<1, NTH>>>(T);
    k_thresholds<<<NTH / 32, 32>>>(T);
    k_wvprefix<<<1, NTH>>>(T);
    dim3 grid((B + 1023) / 1024, (T + TCHUNK - 1) / TCHUNK);
    k_scan<<<grid, 256>>>(u1, u2, (float*)d_out, T, B, (int)(grid.x * grid.y));
}

// round 7
// speedup vs baseline: 3.0181x; 1.0096x over previous
#include <cuda_runtime.h>
#include <math.h>
#include <stdint.h>

#define MAXT_C 10000
#define MAXB_C 4096
#define TCHUNK 16
#define NTH    512
#define ELEMS  20        // ceil(10000/512)
#define NCHUNK ((MAXT_C + TCHUNK - 1) / TCHUNK)

// Scratch (static __device__ arrays: no allocation allowed)
__device__ float   g_f[MAXT_C];          // exp(acts[t])
__device__ float   g_c[MAXT_C];          // LOG_GAMMA + log(1 - f)
__device__ float   g_T2[MAXT_C];         // per-step death threshold: exp(logit_t) - eps
__device__ float   g_u2min[NCHUNK];      // per-chunk screen: death impossible unless u2 > this
__device__ double  g_Wbase[NTH];         // per-segment logw base (incl. INIT_LOGW)
__device__ double  g_Pbase[NTH];         // per-segment logp base (incl. INIT_LOGP)
__device__ double  g_prefix[MAXT_C + 1]; // prefix[k] = sum_{t<k} w_t
__device__ int     g_death[MAXB_C];      // first death step per lane (T if none)
__device__ int     g_tcut;               // no deaths possible for t >= g_tcut
__device__ int     g_done;               // block completion counter for fused reduce

// ---------------------------------------------------------------------------
// K1: wide elementwise transcendentals + state init.
__global__ void __launch_bounds__(512) k_elemwise(const float* __restrict__ acts, int T, int B) {
    const float LOG_GAMMA_F = (float)log(1.02);
    int i = blockIdx.x * 512 + threadIdx.x;
    if (i < T) {
        float f = __expf(acts[i]);
        g_f[i] = f;
        g_c[i] = LOG_GAMMA_F + __logf(1.0f - f);
    }
    if (i < B) g_death[i] = T;
    if (i == 0) { g_done = 0; g_tcut = 0; }
}

// ---------------------------------------------------------------------------
// Exclusive block-wide scan (blockDim.x == NTH), fp64.
__device__ __forceinline__ double block_scan_excl(double v, double& total, double* s_warp) {
    const unsigned FULL = 0xffffffffu;
    int lane = threadIdx.x & 31;
    int w    = threadIdx.x >> 5;
    const int NW = NTH / 32;
    double inc = v;
#pragma unroll
    for (int o = 1; o < 32; o <<= 1) {
        double n = __shfl_up_sync(FULL, inc, o);
        if (lane >= o) inc += n;
    }
    double exc = __shfl_up_sync(FULL, inc, 1);
    if (lane == 0) exc = 0.0;
    if (lane == 31) s_warp[w] = inc;
    __syncthreads();
    if (w == 0 && lane < NW) {
        double i2 = s_warp[lane];
#pragma unroll
        for (int o = 1; o < NW; o <<= 1) {
            double n = __shfl_up_sync((1u << NW) - 1u, i2, o);
            if (lane >= o) i2 += n;
        }
        double e2 = __shfl_up_sync((1u << NW) - 1u, i2, 1);
        if (lane == 0) e2 = 0.0;
        s_warp[lane] = e2;
        if (lane == NW - 1) s_warp[NW] = i2;
    }
    __syncthreads();
    exc += s_warp[w];
    total = s_warp[NW];
    __syncthreads();
    return exc;
}

// exp(x) for tiny |x| without MUFU; fallback for the rare large case.
__device__ __forceinline__ float exp_tiny(float x) {
    if (fabsf(x) < 0.03f)
        return 1.0f + x * (1.0f + x * (0.5f + x * (1.0f / 6.0f)));
    return __expf(x);
}

// ---------------------------------------------------------------------------
// K2: single-block. Three fp64 block scans (W, P, reward-prefix). MUFU per
// element avoided via multiplicative chains; writes g_prefix inline.
__global__ void __launch_bounds__(NTH, 1) k_scanbases(int T) {
    __shared__ double s_warp[NTH / 32 + 1];
    int tid = threadIdx.x;
    int seg = tid * ELEMS;

    const float ALPHA_F     = (float)(log(0.99) / 1000.0);
    const float INIT_LOGW_F = (float)log(0.248);
    const float INIT_LOGP_F = (float)log(0.001);

    // ---- pass 1: load f, c; segment c-sum; scan -> Wbase ----
    float fArr[ELEMS], cArr[ELEMS];
    float csum = 0.0f;
#pragma unroll
    for (int j = 0; j < ELEMS; j++) {
        int i = seg + j;
        float f = 0.0f, c = 0.0f;
        if (i < T) { f = g_f[i]; c = g_c[i]; }
        fArr[j] = f; cArr[j] = c;
        csum += c;
    }
    double tot;
    double Wbase_d = block_scan_excl((double)csum, tot, s_warp) + (double)INIT_LOGW_F;
    g_Wbase[tid] = Wbase_d;

    // ---- pass 2: df chain -> scan -> Pbase ----
    float dfsum = 0.0f;
    {
        float ew = __expf((float)Wbase_d);
#pragma unroll
        for (int j = 0; j < ELEMS; j++) {
            int i = seg + j;
            if (i < T) {
                dfsum += ALPHA_F * fArr[j] * ew;
                ew *= 1.02f * (1.0f - fArr[j]);   // = ew * e^{c_j}
            }
        }
    }
    double Pbase_d = block_scan_excl((double)dfsum, tot, s_warp) + (double)INIT_LOGP_F;
    g_Pbase[tid] = Pbase_d;

    // ---- pass 3: reward weights via multiplicative chain (no per-elem MUFU):
    //      wv_j = exp(W_{j+1}/1000) = exp(Wbase/1000) * prod m_k, m = exp(c/1000)
    float wvArr[ELEMS];
    float wvsum = 0.0f;
    {
        float v = __expf((float)Wbase_d * 0.001f);
#pragma unroll
        for (int j = 0; j < ELEMS; j++) {
            int i = seg + j;
            float wv = 0.0f;
            if (i < T) {
                v *= exp_tiny(cArr[j] * 0.001f);
                wv = v;
            }
            wvArr[j] = wv;
            wvsum += wv;
        }
    }
    double Sbase = block_scan_excl((double)wvsum, tot, s_warp);
    {
        float ls = 0.0f;
#pragma unroll
        for (int j = 0; j < ELEMS; j++) {
            int i = seg + j;
            if (i < T) g_prefix[i] = Sbase + (double)ls;
            ls += wvArr[j];
        }
    }
    if (tid == 0) g_prefix[T] = tot;
}

// ---------------------------------------------------------------------------
// K3: wide elementwise heavy-MUFU pass (thresholds, screen, tcut).
__global__ void __launch_bounds__(32) k_thresholds(int T) {
    int s = blockIdx.x * 32 + threadIdx.x;
    int seg = s * ELEMS;
    const float ALPHA_F = (float)(log(0.99) / 1000.0);

    float Wbase = (float)g_Wbase[s];
    float Pbase = (float)g_Pbase[s];
    float ew = __expf(Wbase);
    float lp = 0.0f;
    int tmax = 0;
#pragma unroll
    for (int j = 0; j < ELEMS; j++) {
        int i = seg + j;
        if (i < T) {
            float f = g_f[i];
            float q = __expf(Pbase + lp);
            float thr = __fdividef(q, 1.0f - q);        // = exp(logit)
            float T2  = thr - 1e-12f;
            g_T2[i] = T2;
            if ((i & (TCHUNK - 1)) == 0)                 // T2 monotone decreasing in t
                g_u2min[i / TCHUNK] = __expf(-27.64f * T2) * (1.0f - 1e-5f);
            if (q >= 1.4e-11f) tmax = i + 1;             // logit >= -25 (noise <= ~20)
            lp += ALPHA_F * f * ew;
            ew *= 1.02f * (1.0f - f);
        }
    }
#pragma unroll
    for (int o = 16; o > 0; o >>= 1) tmax = max(tmax, __shfl_down_sync(0xffffffffu, tmax, o));
    if (threadIdx.x == 0 && tmax > 0) atomicMax(&g_tcut, tmax);
}

// ---------------------------------------------------------------------------
// K5: screened death scan (vec4 over lanes) + fused final reduce.
__global__ void __launch_bounds__(256) k_scan(const float* __restrict__ u1,
                                              const float* __restrict__ u2,
                                              float* __restrict__ out,
                                              int T, int B, int nblocks) {
    int tstart = blockIdx.y * TCHUNK;
    __shared__ float s_T2[TCHUNK];
    bool active = (tstart < g_tcut);          // uniform per block
    if (active) {
        if (threadIdx.x < TCHUNK) {
            int t = tstart + threadIdx.x;
            s_T2[threadIdx.x] = (t < T) ? g_T2[t] : -1.0f;
        }
        __syncthreads();
        float u2min = g_u2min[blockIdx.y];
        int b4 = (blockIdx.x * blockDim.x + threadIdx.x) * 4;
        if (b4 + 3 < B) {
            const float4* u2v = (const float4*)u2;
            int tend = min(TCHUNK, T - tstart);
            unsigned m0 = 0, m1 = 0, m2 = 0, m3 = 0;
#pragma unroll
            for (int t = 0; t < TCHUNK; t++) {
                if (t < tend) {
                    float4 v = u2v[((size_t)(tstart + t) * B + b4) >> 2];
                    if (v.x > u2min) m0 |= 1u << t;
                    if (v.y > u2min) m1 |= 1u << t;
                    if (v.z > u2min) m2 |= 1u << t;
                    if (v.w > u2min) m3 |= 1u << t;
                }
            }
            const float EPSF = 1e-12f;
#pragma unroll
            for (int l = 0; l < 4; l++) {
                unsigned m = (l == 0) ? m0 : (l == 1) ? m1 : (l == 2) ? m2 : m3;
                while (m) {
                    int t = __ffs(m) - 1;
                    m &= m - 1;
                    size_t idx = (size_t)(tstart + t) * B + b4 + l;
                    float la = __logf(u2[idx] + EPSF);
                    float lb = __logf(u1[idx] + EPSF);
                    if (la > s_T2[t] * lb) {
                        atomicMin(&g_death[b4 + l], tstart + t);
                        break;              // bits ascend in t: first hit = chunk minimum
                    }
                }
            }
        }
        __syncthreads();
    }

    // ---- completion protocol: last block reduces ----
    __threadfence();
    __shared__ int lastFlag;
    if (threadIdx.x == 0)
        lastFlag = (atomicAdd(&g_done, 1) == nblocks - 1);
    __syncthreads();
    if (!lastFlag) return;

    __shared__ double s_red[8];
    double s = 0.0;
    for (int i = threadIdx.x; i < B; i += 256) s += g_prefix[g_death[i]];
#pragma unroll
    for (int o = 16; o > 0; o >>= 1) s += __shfl_down_sync(0xffffffffu, s, o);
    if ((threadIdx.x & 31) == 0) s_red[threadIdx.x >> 5] = s;
    __syncthreads();
    if (threadIdx.x < 8) {
        double v = s_red[threadIdx.x];
#pragma unroll
        for (int o = 4; o > 0; o >>= 1) v += __shfl_down_sync(0xffu, v, o);
        if (threadIdx.x == 0) out[0] = (float)(v / (double)B);
    }
}

extern "C" void kernel_launch(void* const* d_in, const int* in_sizes, int n_in,
                              void* d_out, int out_size) {
    const float* acts = (const float*)d_in[0];
    const float* u1   = (const float*)d_in[1];
    const float* u2   = (const float*)d_in[2];
    int T = in_sizes[0];
    int B = (T > 0) ? (in_sizes[1] / T) : 0;

    int initN = (T > B) ? T : B;
    k_elemwise<<<(initN + 511) / 512, 512>>>(acts, T, B);
    k_scanbases<<<1, NTH>>>(T);
    k_thresholds<<<NTH / 32, 32>>>(T);
    dim3 grid((B + 1023) / 1024, (T + TCHUNK - 1) / TCHUNK);
    k_scan<<<grid, 256>>>(u1, u2, (float*)d_out, T, B, (int)(grid.x * grid.y));
}

// round 8
// speedup vs baseline: 3.0906x; 1.0240x over previous
#include <cuda_runtime.h>
#include <math.h>
#include <stdint.h>

#define MAXT_C 10000
#define MAXB_C 4096
#define TCHUNK 16
#define NTH    512
#define ELEMS  20        // ceil(10000/512)
#define NCHUNK ((MAXT_C + TCHUNK - 1) / TCHUNK)

// Scratch (static __device__ arrays: no allocation allowed)
__device__ float   g_f[MAXT_C];          // exp(acts[t])
__device__ float   g_c[MAXT_C];          // LOG_GAMMA + log(1 - f)
__device__ float   g_T2[MAXT_C];         // per-step death threshold: exp(logit_t) - eps
__device__ float   g_u2min[NCHUNK];      // per-chunk screen: death impossible unless u2 > this
__device__ double  g_prefix[MAXT_C + 1]; // prefix[k] = sum_{t<k} w_t
__device__ int     g_death[MAXB_C];      // first death step per lane (T if none)
__device__ int     g_tcut;               // no deaths possible for t >= g_tcut
__device__ int     g_done;               // block completion counter for fused reduce

// ---------------------------------------------------------------------------
// K1: wide elementwise transcendentals + state init.
__global__ void __launch_bounds__(512) k_elemwise(const float* __restrict__ acts, int T, int B) {
    const float LOG_GAMMA_F = (float)log(1.02);
    int i = blockIdx.x * 512 + threadIdx.x;
    if (i < T) {
        float f = __expf(acts[i]);
        g_f[i] = f;
        g_c[i] = LOG_GAMMA_F + __logf(1.0f - f);
    }
    if (i < B) g_death[i] = T;
    if (i == 0) g_done = 0;
}

// ---------------------------------------------------------------------------
// Exclusive block-wide scan (blockDim.x == NTH), fp64.
__device__ __forceinline__ double block_scan_excl(double v, double& total, double* s_warp) {
    const unsigned FULL = 0xffffffffu;
    int lane = threadIdx.x & 31;
    int w    = threadIdx.x >> 5;
    const int NW = NTH / 32;
    double inc = v;
#pragma unroll
    for (int o = 1; o < 32; o <<= 1) {
        double n = __shfl_up_sync(FULL, inc, o);
        if (lane >= o) inc += n;
    }
    double exc = __shfl_up_sync(FULL, inc, 1);
    if (lane == 0) exc = 0.0;
    if (lane == 31) s_warp[w] = inc;
    __syncthreads();
    if (w == 0 && lane < NW) {
        double i2 = s_warp[lane];
#pragma unroll
        for (int o = 1; o < NW; o <<= 1) {
            double n = __shfl_up_sync((1u << NW) - 1u, i2, o);
            if (lane >= o) i2 += n;
        }
        double e2 = __shfl_up_sync((1u << NW) - 1u, i2, 1);
        if (lane == 0) e2 = 0.0;
        s_warp[lane] = e2;
        if (lane == NW - 1) s_warp[NW] = i2;
    }
    __syncthreads();
    exc += s_warp[w];
    total = s_warp[NW];
    __syncthreads();
    return exc;
}

// exp(x) for tiny |x| without MUFU; fallback for the rare large case.
__device__ __forceinline__ float exp_tiny(float x) {
    if (fabsf(x) < 0.03f)
        return 1.0f + x * (1.0f + x * (0.5f + x * (1.0f / 6.0f)));
    return __expf(x);
}

// ---------------------------------------------------------------------------
// K2: single-block. Three fp64 block scans (W, P, reward-prefix), plus the
// full threshold/screen pass — all via multiplicative chains, no per-element
// MUFU (q <= 0.001 so thr = q(1+q+q^2); |df| < 0.03 in the live region).
__global__ void __launch_bounds__(NTH, 1) k_scanbases(int T) {
    __shared__ double s_warp[NTH / 32 + 1];
    __shared__ int s_imax[NTH / 32];
    int tid = threadIdx.x;
    int seg = tid * ELEMS;

    const float ALPHA_F     = (float)(log(0.99) / 1000.0);
    const float INIT_LOGW_F = (float)log(0.248);
    const float INIT_LOGP_F = (float)log(0.001);

    // ---- pass 1: load f, c; segment c-sum; wv multipliers m = e^{c/1000} ----
    float fArr[ELEMS], mArr[ELEMS];
    float csum = 0.0f;
#pragma unroll
    for (int j = 0; j < ELEMS; j++) {
        int i = seg + j;
        float f = 0.0f, c = 0.0f;
        if (i < T) { f = g_f[i]; c = g_c[i]; }
        fArr[j] = f;
        mArr[j] = exp_tiny(c * 0.001f);
        csum += c;
    }
    double tot;
    double Wbase_d = block_scan_excl((double)csum, tot, s_warp) + (double)INIT_LOGW_F;
    float  Wbase   = (float)Wbase_d;

    // ---- pass 2: df chain -> segment dfsum -> scan -> Pbase ----
    float dfsum = 0.0f;
    {
        float ew = __expf(Wbase);
#pragma unroll
        for (int j = 0; j < ELEMS; j++) {
            int i = seg + j;
            if (i < T) {
                dfsum += ALPHA_F * fArr[j] * ew;
                ew *= 1.02f * (1.0f - fArr[j]);   // = ew * e^{c_j}
            }
        }
    }
    double Pbase_d = block_scan_excl((double)dfsum, tot, s_warp) + (double)INIT_LOGP_F;

    // ---- pass 3: thresholds (q chain), screen, tcut, reward weights ----
    float wvArr[ELEMS];
    float wvsum = 0.0f;
    int tmax = 0;
    {
        float ew = __expf(Wbase);
        float q  = __expf((float)Pbase_d);          // e^{logp entering segment}
        float v  = __expf(Wbase * 0.001f);
#pragma unroll
        for (int j = 0; j < ELEMS; j++) {
            int i = seg + j;
            float wv = 0.0f;
            if (i < T) {
                float thr = q * (1.0f + q + q * q);     // = q/(1-q), q <= 1e-3
                float T2  = thr - 1e-12f;
                g_T2[i] = T2;
                if ((i & (TCHUNK - 1)) == 0)            // T2 monotone decreasing in t
                    g_u2min[i / TCHUNK] = exp_tiny(-27.64f * T2) * (1.0f - 1e-5f);
                if (q >= 1.4e-11f) tmax = i + 1;        // logit >= -25 (noise <= ~20)
                float df = ALPHA_F * fArr[j] * ew;
                q = (q >= 1e-13f) ? q * exp_tiny(df) : 0.0f;
                ew *= 1.02f * (1.0f - fArr[j]);
                v *= mArr[j];                           // wv = e^{W_{i+1}/1000}
                wv = v;
            }
            wvArr[j] = wv;
            wvsum += wv;
        }
    }
    double Sbase = block_scan_excl((double)wvsum, tot, s_warp);
    {
        float ls = 0.0f;
#pragma unroll
        for (int j = 0; j < ELEMS; j++) {
            int i = seg + j;
            if (i < T) g_prefix[i] = Sbase + (double)ls;
            ls += wvArr[j];
        }
    }
    if (tid == 0) g_prefix[T] = tot;

    // ---- block max-reduce for tcut ----
#pragma unroll
    for (int o = 16; o > 0; o >>= 1) tmax = max(tmax, __shfl_down_sync(0xffffffffu, tmax, o));
    if ((tid & 31) == 0) s_imax[tid >> 5] = tmax;
    __syncthreads();
    if (tid < NTH / 32) {
        int v = s_imax[tid];
#pragma unroll
        for (int o = (NTH / 64); o > 0; o >>= 1)
            v = max(v, __shfl_down_sync((1u << (NTH / 32)) - 1u, v, o));
        if (tid == 0) g_tcut = v;
    }
}

// ---------------------------------------------------------------------------
// K3: screened death scan + fused final reduce. Loads front-batched into a
// register array (128-reg budget via launch_bounds) for max MLP.
__global__ void __launch_bounds__(256, 2) k_scan(const float* __restrict__ u1,
                                                 const float* __restrict__ u2,
                                                 float* __restrict__ out,
                                                 int T, int B, int nblocks) {
    int tstart = blockIdx.y * TCHUNK;
    __shared__ float s_T2[TCHUNK];
    bool active = (tstart < g_tcut);          // uniform per block
    if (active) {
        if (threadIdx.x < TCHUNK) {
            int t = tstart + threadIdx.x;
            s_T2[threadIdx.x] = (t < T) ? g_T2[t] : -1.0f;
        }
        __syncthreads();
        float u2min = g_u2min[blockIdx.y];
        int b4 = (blockIdx.x * blockDim.x + threadIdx.x) * 4;
        if (b4 + 3 < B) {
            const float4* u2v = (const float4*)u2;
            float4 v[TCHUNK];
            if (tstart + TCHUNK <= T) {
#pragma unroll
                for (int t = 0; t < TCHUNK; t++)
                    v[t] = u2v[((size_t)(tstart + t) * B + b4) >> 2];
            } else {
#pragma unroll
                for (int t = 0; t < TCHUNK; t++)
                    v[t] = (tstart + t < T) ? u2v[((size_t)(tstart + t) * B + b4) >> 2]
                                            : make_float4(0.f, 0.f, 0.f, 0.f);
            }
            unsigned m0 = 0, m1 = 0, m2 = 0, m3 = 0;
#pragma unroll
            for (int t = 0; t < TCHUNK; t++) {
                if (v[t].x > u2min) m0 |= 1u << t;
                if (v[t].y > u2min) m1 |= 1u << t;
                if (v[t].z > u2min) m2 |= 1u << t;
                if (v[t].w > u2min) m3 |= 1u << t;
            }
            const float EPSF = 1e-12f;
#pragma unroll
            for (int l = 0; l < 4; l++) {
                unsigned m = (l == 0) ? m0 : (l == 1) ? m1 : (l == 2) ? m2 : m3;
                while (m) {
                    int t = __ffs(m) - 1;
                    m &= m - 1;
                    size_t idx = (size_t)(tstart + t) * B + b4 + l;
                    float la = __logf(u2[idx] + EPSF);
                    float lb = __logf(u1[idx] + EPSF);
                    if (la > s_T2[t] * lb) {
                        atomicMin(&g_death[b4 + l], tstart + t);
                        break;              // bits ascend in t: first hit = chunk minimum
                    }
                }
            }
        }
        __syncthreads();
    }

    // ---- completion protocol: last block reduces ----
    __threadfence();
    __shared__ int lastFlag;
    if (threadIdx.x == 0)
        lastFlag = (atomicAdd(&g_done, 1) == nblocks - 1);
    __syncthreads();
    if (!lastFlag) return;

    __shared__ double s_red[8];
    double s = 0.0;
    for (int i = threadIdx.x; i < B; i += 256) s += g_prefix[g_death[i]];
#pragma unroll
    for (int o = 16; o > 0; o >>= 1) s += __shfl_down_sync(0xffffffffu, s, o);
    if ((threadIdx.x & 31) == 0) s_red[threadIdx.x >> 5] = s;
    __syncthreads();
    if (threadIdx.x < 8) {
        double v = s_red[threadIdx.x];
#pragma unroll
        for (int o = 4; o > 0; o >>= 1) v += __shfl_down_sync(0xffu, v, o);
        if (threadIdx.x == 0) out[0] = (float)(v / (double)B);
    }
}

extern "C" void kernel_launch(void* const* d_in, const int* in_sizes, int n_in,
                              void* d_out, int out_size) {
    const float* acts = (const float*)d_in[0];
    const float* u1   = (const float*)d_in[1];
    const float* u2   = (const float*)d_in[2];
    int T = in_sizes[0];
    int B = (T > 0) ? (in_sizes[1] / T) : 0;

    int initN = (T > B) ? T : B;
    k_elemwise<<<(initN + 511) / 512, 512>>>(acts, T, B);
    k_scanbases<<<1, NTH>>>(T);
    dim3 grid((B + 1023) / 1024, (T + TCHUNK - 1) / TCHUNK);
    k_scan<<<grid, 256>>>(u1, u2, (float*)d_out, T, B, (int)(grid.x * grid.y));
}

// round 9
// speedup vs baseline: 3.2320x; 1.0457x over previous
#include <cuda_runtime.h>
#include <math.h>
#include <stdint.h>

#define MAXT_C 10000
#define MAXB_C 4096
#define TCHUNK 16
#define NTH    512
#define ELEMS  20        // ceil(10000/512)
#define NCHUNK ((MAXT_C + TCHUNK - 1) / TCHUNK)
#define GRIDY  74        // persistent grid: 2 x 74 = 148 blocks = 1 wave @ 1 block/SM

// Scratch (static __device__ arrays: no allocation allowed)
__device__ float   g_f[MAXT_C];          // exp(acts[t])
__device__ float   g_c[MAXT_C];          // LOG_GAMMA + log(1 - f)
__device__ float   g_T2[MAXT_C];         // per-step death threshold: exp(logit_t) - eps
__device__ float   g_u2min[NCHUNK];      // per-chunk screen: death impossible unless u2 > this
__device__ double  g_prefix[MAXT_C + 1]; // prefix[k] = sum_{t<k} w_t
__device__ int     g_death[MAXB_C];      // first death step per lane (T if none)
__device__ int     g_tcut;               // no deaths possible for t >= g_tcut
__device__ int     g_elemdone;           // phase-1 completion counter  (reset by last block)
__device__ int     g_flag;               // phase-2 publication flag    (reset by last block)
__device__ int     g_done;               // phase-4 completion counter  (reset by last block)

// ---------------------------------------------------------------------------
// Exclusive block-wide scan (blockDim.x == NTH), fp64.
__device__ __forceinline__ double block_scan_excl(double v, double& total, double* s_warp) {
    const unsigned FULL = 0xffffffffu;
    int lane = threadIdx.x & 31;
    int w    = threadIdx.x >> 5;
    const int NW = NTH / 32;
    double inc = v;
#pragma unroll
    for (int o = 1; o < 32; o <<= 1) {
        double n = __shfl_up_sync(FULL, inc, o);
        if (lane >= o) inc += n;
    }
    double exc = __shfl_up_sync(FULL, inc, 1);
    if (lane == 0) exc = 0.0;
    if (lane == 31) s_warp[w] = inc;
    __syncthreads();
    if (w == 0 && lane < NW) {
        double i2 = s_warp[lane];
#pragma unroll
        for (int o = 1; o < NW; o <<= 1) {
            double n = __shfl_up_sync((1u << NW) - 1u, i2, o);
            if (lane >= o) i2 += n;
        }
        double e2 = __shfl_up_sync((1u << NW) - 1u, i2, 1);
        if (lane == 0) e2 = 0.0;
        s_warp[lane] = e2;
        if (lane == NW - 1) s_warp[NW] = i2;
    }
    __syncthreads();
    exc += s_warp[w];
    total = s_warp[NW];
    __syncthreads();
    return exc;
}

// exp(x) for tiny |x| without MUFU; fallback for the rare large case.
__device__ __forceinline__ float exp_tiny(float x) {
    if (fabsf(x) < 0.03f)
        return 1.0f + x * (1.0f + x * (0.5f + x * (1.0f / 6.0f)));
    return __expf(x);
}

// ---------------------------------------------------------------------------
// Phase 2 body (block 0 only): three fp64 block scans (W, P, reward-prefix),
// thresholds/screen via multiplicative chains — no per-element MUFU.
__device__ void scanbases_body(int T) {
    __shared__ double s_warp[NTH / 32 + 1];
    __shared__ int s_imax[NTH / 32];
    int tid = threadIdx.x;
    int seg = tid * ELEMS;

    const float ALPHA_F     = (float)(log(0.99) / 1000.0);
    const float INIT_LOGW_F = (float)log(0.248);
    const float INIT_LOGP_F = (float)log(0.001);

    // pass 1: f, c; segment c-sum; wv multipliers m = e^{c/1000}
    float fArr[ELEMS], mArr[ELEMS];
    float csum = 0.0f;
#pragma unroll
    for (int j = 0; j < ELEMS; j++) {
        int i = seg + j;
        float f = 0.0f, c = 0.0f;
        if (i < T) { f = g_f[i]; c = g_c[i]; }
        fArr[j] = f;
        mArr[j] = exp_tiny(c * 0.001f);
        csum += c;
    }
    double tot;
    double Wbase_d = block_scan_excl((double)csum, tot, s_warp) + (double)INIT_LOGW_F;
    float  Wbase   = (float)Wbase_d;

    // pass 2: df chain -> scan -> Pbase
    float dfsum = 0.0f;
    {
        float ew = __expf(Wbase);
#pragma unroll
        for (int j = 0; j < ELEMS; j++) {
            int i = seg + j;
            if (i < T) {
                dfsum += ALPHA_F * fArr[j] * ew;
                ew *= 1.02f * (1.0f - fArr[j]);   // = ew * e^{c_j}
            }
        }
    }
    double Pbase_d = block_scan_excl((double)dfsum, tot, s_warp) + (double)INIT_LOGP_F;

    // pass 3: thresholds (q chain), screen, tcut, reward weights
    float wvArr[ELEMS];
    float wvsum = 0.0f;
    int tmax = 0;
    {
        float ew = __expf(Wbase);
        float q  = __expf((float)Pbase_d);          // e^{logp entering segment}
        float v  = __expf(Wbase * 0.001f);
#pragma unroll
        for (int j = 0; j < ELEMS; j++) {
            int i = seg + j;
            float wv = 0.0f;
            if (i < T) {
                float thr = q * (1.0f + q + q * q);     // = q/(1-q), q <= 1e-3
                float T2  = thr - 1e-12f;
                g_T2[i] = T2;
                if ((i & (TCHUNK - 1)) == 0)            // T2 monotone decreasing in t
                    g_u2min[i / TCHUNK] = exp_tiny(-27.64f * T2) * (1.0f - 1e-5f);
                if (q >= 1.4e-11f) tmax = i + 1;        // logit >= -25 (noise <= ~20)
                float df = ALPHA_F * fArr[j] * ew;
                q = (q >= 1e-13f) ? q * exp_tiny(df) : 0.0f;
                ew *= 1.02f * (1.0f - fArr[j]);
                v *= mArr[j];                           // wv = e^{W_{i+1}/1000}
                wv = v;
            }
            wvArr[j] = wv;
            wvsum += wv;
        }
    }
    double Sbase = block_scan_excl((double)wvsum, tot, s_warp);
    {
        float ls = 0.0f;
#pragma unroll
        for (int j = 0; j < ELEMS; j++) {
            int i = seg + j;
            if (i < T) g_prefix[i] = Sbase + (double)ls;
            ls += wvArr[j];
        }
    }
    if (tid == 0) g_prefix[T] = tot;

    // tcut block max-reduce
#pragma unroll
    for (int o = 16; o > 0; o >>= 1) tmax = max(tmax, __shfl_down_sync(0xffffffffu, tmax, o));
    if ((tid & 31) == 0) s_imax[tid >> 5] = tmax;
    __syncthreads();
    if (tid < NTH / 32) {
        int v = s_imax[tid];
#pragma unroll
        for (int o = (NTH / 64); o > 0; o >>= 1)
            v = max(v, __shfl_down_sync((1u << (NTH / 32)) - 1u, v, o));
        if (tid == 0) g_tcut = v;
    }
}

// ---------------------------------------------------------------------------
__device__ __forceinline__ void load_chunk(float4 v[TCHUNK], const float4* __restrict__ u2v,
                                           int tstart, int b4, int T, int B) {
#pragma unroll
    for (int t = 0; t < TCHUNK; t++)
        v[t] = (tstart + t < T) ? u2v[((size_t)(tstart + t) * B + b4) >> 2]
                                : make_float4(0.f, 0.f, 0.f, 0.f);
}

__device__ __forceinline__ void process_chunk(const float4 v[TCHUNK], int tstart, int b4,
                                              const float* __restrict__ u1,
                                              const float* __restrict__ u2,
                                              float u2min, int B) {
    unsigned m0 = 0, m1 = 0, m2 = 0, m3 = 0;
#pragma unroll
    for (int t = 0; t < TCHUNK; t++) {
        if (v[t].x > u2min) m0 |= 1u << t;
        if (v[t].y > u2min) m1 |= 1u << t;
        if (v[t].z > u2min) m2 |= 1u << t;
        if (v[t].w > u2min) m3 |= 1u << t;
    }
    const float EPSF = 1e-12f;
#pragma unroll
    for (int l = 0; l < 4; l++) {
        unsigned m = (l == 0) ? m0 : (l == 1) ? m1 : (l == 2) ? m2 : m3;
        if (m && g_death[b4 + l] > tstart) {
            while (m) {
                int t = __ffs(m) - 1;
                m &= m - 1;
                size_t idx = (size_t)(tstart + t) * B + b4 + l;
                float la = __logf(u2[idx] + EPSF);
                float lb = __logf(u1[idx] + EPSF);
                if (la > g_T2[tstart + t] * lb) {
                    atomicMin(&g_death[b4 + l], tstart + t);
                    break;              // bits ascend in t: first hit = chunk minimum
                }
            }
        }
    }
}

// ---------------------------------------------------------------------------
// Single fused kernel. Grid = (ceil(B/2048), GRIDY) = 148 blocks, 1 block/SM,
// all resident in wave 1 => internal flag-spins are deadlock-free.
__global__ void __launch_bounds__(NTH, 1)
k_all(const float* __restrict__ acts, const float* __restrict__ u1,
      const float* __restrict__ u2, float* __restrict__ out,
      int T, int B, int nelem, int nblocks) {
    int tid  = threadIdx.x;
    int flat = blockIdx.y * gridDim.x + blockIdx.x;
    bool producer = (flat == 0);

    // ---- Phase 1: wide elementwise (first nelem blocks) ----
    if (flat < nelem) {
        const float LOG_GAMMA_F = (float)log(1.02);
        int i = flat * NTH + tid;
        if (i < T) {
            float f = __expf(acts[i]);
            g_f[i] = f;
            g_c[i] = LOG_GAMMA_F + __logf(1.0f - f);
        }
        if (i < B) g_death[i] = T;
        __syncthreads();
        if (tid == 0) { __threadfence(); atomicAdd(&g_elemdone, 1); }
    }

    int b4 = (blockIdx.x * NTH + tid) * 4;
    bool lanes_ok = (b4 + 3 < B);
    const float4* u2v = (const float4*)u2;

    if (producer) {
        // ---- Phase 2: scan bases / thresholds / prefix (this block only) ----
        if (tid == 0) { while (atomicAdd(&g_elemdone, 0) < nelem) __nanosleep(64); }
        __syncthreads();
        __threadfence();
        scanbases_body(T);
        __syncthreads();
        if (tid == 0) { __threadfence(); atomicExch(&g_flag, 1); }
        __syncthreads();
        // ---- Phase 3 (producer's chunks, normal loads) ----
        int tcut = g_tcut;
        for (int chunk = blockIdx.y; chunk * TCHUNK < tcut; chunk += gridDim.y) {
            if (lanes_ok) {
                float4 v[TCHUNK];
                load_chunk(v, u2v, chunk * TCHUNK, b4, T, B);
                process_chunk(v, chunk * TCHUNK, b4, u1, u2, g_u2min[chunk], B);
            }
        }
    } else {
        // ---- overlap: prefetch this block's first chunk while phase 2 runs ----
        float4 v[TCHUNK];
        int pchunk = blockIdx.y;
        if (lanes_ok) load_chunk(v, u2v, pchunk * TCHUNK, b4, T, B);
        if (tid == 0) {
            volatile int* vf = &g_flag;
            while (*vf == 0) __nanosleep(128);
        }
        __syncthreads();
        __threadfence();
        int tcut = g_tcut;
        if (lanes_ok && pchunk * TCHUNK < tcut)
            process_chunk(v, pchunk * TCHUNK, b4, u1, u2, g_u2min[pchunk], B);
        for (int chunk = pchunk + gridDim.y; chunk * TCHUNK < tcut; chunk += gridDim.y) {
            if (lanes_ok) {
                float4 w[TCHUNK];
                load_chunk(w, u2v, chunk * TCHUNK, b4, T, B);
                process_chunk(w, chunk * TCHUNK, b4, u1, u2, g_u2min[chunk], B);
            }
        }
    }

    // ---- Phase 4: last block reduces, then resets sync state for next replay ----
    __threadfence();
    __shared__ int lastFlag;
    if (tid == 0) lastFlag = (atomicAdd(&g_done, 1) == nblocks - 1);
    __syncthreads();
    if (!lastFlag) return;

    __shared__ double s_red[NTH / 32];
    double s = 0.0;
    for (int i = tid; i < B; i += NTH) s += g_prefix[g_death[i]];
#pragma unroll
    for (int o = 16; o > 0; o >>= 1) s += __shfl_down_sync(0xffffffffu, s, o);
    if ((tid & 31) == 0) s_red[tid >> 5] = s;
    __syncthreads();
    if (tid < NTH / 32) {
        double v = s_red[tid];
#pragma unroll
        for (int o = NTH / 64; o > 0; o >>= 1)
            v += __shfl_down_sync((1u << (NTH / 32)) - 1u, v, o);
        if (tid == 0) {
            out[0] = (float)(v / (double)B);
            g_flag = 0;                 // safe: all blocks already passed the flag wait
            g_elemdone = 0;
            g_done = 0;
        }
    }
}

extern "C" void kernel_launch(void* const* d_in, const int* in_sizes, int n_in,
                              void* d_out, int out_size) {
    const float* acts = (const float*)d_in[0];
    const float* u1   = (const float*)d_in[1];
    const float* u2   = (const float*)d_in[2];
    int T = in_sizes[0];
    int B = (T > 0) ? (in_sizes[1] / T) : 0;

    int gx = (B + NTH * 4 - 1) / (NTH * 4);           // 2 for B=4096
    dim3 grid(gx, GRIDY);                             // 148 blocks total
    int nblocks = gx * GRIDY;
    int maxTB = (T > B) ? T : B;
    int nelem = (maxTB + NTH - 1) / NTH;              // 20
    k_all<<<grid, NTH>>>(acts, u1, u2, (float*)d_out, T, B, nelem, nblocks);
}

// round 10
// speedup vs baseline: 3.3710x; 1.0430x over previous
#include <cuda_runtime.h>
#include <math.h>
#include <stdint.h>

#define MAXT_C 10000
#define PADT   10240     // NTH * ELEMS, zero-padded so phase-2 float4 loads are unguarded
#define MAXB_C 4096
#define TCHUNK 16
#define NTH    512
#define ELEMS  20        // ceil(10000/512)
#define NCHUNK ((MAXT_C + TCHUNK - 1) / TCHUNK)
#define GRIDY  74        // persistent grid: 2 x 74 = 148 blocks = 1 wave @ 1 block/SM

// Scratch (static __device__ arrays: no allocation allowed)
__device__ float   g_f[PADT];            // exp(acts[t]), zero past T
__device__ float   g_c[PADT];            // LOG_GAMMA + log(1 - f), zero past T
__device__ float   g_T2[MAXT_C];         // per-step death threshold: exp(logit_t) - eps
__device__ float   g_u2min[NCHUNK];      // per-chunk screen: death impossible unless u2 > this
__device__ double  g_prefix[MAXT_C + 1]; // prefix[k] = sum_{t<k} w_t
__device__ int     g_death[MAXB_C];      // first death step per lane (T if none)
__device__ int     g_tcut;               // no deaths possible for t >= g_tcut
__device__ int     g_elemdone;           // phase-1 completion counter  (reset by last block)
__device__ int     g_flag;               // phase-2 publication flag    (reset by last block)
__device__ int     g_done;               // phase-4 completion counter  (reset by last block)

// ---------------------------------------------------------------------------
// Exclusive block-wide scan (blockDim.x == NTH), fp64.
__device__ __forceinline__ double block_scan_excl(double v, double& total, double* s_warp) {
    const unsigned FULL = 0xffffffffu;
    int lane = threadIdx.x & 31;
    int w    = threadIdx.x >> 5;
    const int NW = NTH / 32;
    double inc = v;
#pragma unroll
    for (int o = 1; o < 32; o <<= 1) {
        double n = __shfl_up_sync(FULL, inc, o);
        if (lane >= o) inc += n;
    }
    double exc = __shfl_up_sync(FULL, inc, 1);
    if (lane == 0) exc = 0.0;
    if (lane == 31) s_warp[w] = inc;
    __syncthreads();
    if (w == 0 && lane < NW) {
        double i2 = s_warp[lane];
#pragma unroll
        for (int o = 1; o < NW; o <<= 1) {
            double n = __shfl_up_sync((1u << NW) - 1u, i2, o);
            if (lane >= o) i2 += n;
        }
        double e2 = __shfl_up_sync((1u << NW) - 1u, i2, 1);
        if (lane == 0) e2 = 0.0;
        s_warp[lane] = e2;
        if (lane == NW - 1) s_warp[NW] = i2;
    }
    __syncthreads();
    exc += s_warp[w];
    total = s_warp[NW];
    __syncthreads();
    return exc;
}

// exp(x) for tiny |x| without MUFU; fallback for the rare large case.
__device__ __forceinline__ float exp_tiny(float x) {
    if (fabsf(x) < 0.03f)
        return 1.0f + x * (1.0f + x * (0.5f + x * (1.0f / 6.0f)));
    return __expf(x);
}

// ---------------------------------------------------------------------------
// Phase 2 body (block 0 only). No per-thread arrays: each pass re-loads its
// 20 contiguous f/c values as 5 float4 loads (L1/L2-hot) => no spills.
__device__ void scanbases_body(int T) {
    __shared__ double s_warp[NTH / 32 + 1];
    __shared__ int s_imax[NTH / 32];
    int tid = threadIdx.x;
    int seg = tid * ELEMS;
    const float4* f4 = (const float4*)g_f;   // seg*4 bytes is 16B-aligned (80*tid)
    const float4* c4 = (const float4*)g_c;

    const float ALPHA_F     = (float)(log(0.99) / 1000.0);
    const float INIT_LOGW_F = (float)log(0.248);
    const float INIT_LOGP_F = (float)log(0.001);

    // pass 1: segment c-sum
    float csum = 0.0f;
#pragma unroll
    for (int k = 0; k < ELEMS / 4; k++) {
        float4 c = c4[(seg >> 2) + k];
        csum += c.x + c.y + c.z + c.w;
    }
    double tot;
    double Wbase_d = block_scan_excl((double)csum, tot, s_warp) + (double)INIT_LOGW_F;
    float  Wbase   = (float)Wbase_d;

    // pass 2: df chain -> segment dfsum (pad f=0 contributes 0)
    float dfsum = 0.0f;
    {
        float ew = __expf(Wbase);
#pragma unroll
        for (int k = 0; k < ELEMS / 4; k++) {
            float4 f = f4[(seg >> 2) + k];
            dfsum += ALPHA_F * f.x * ew; ew *= 1.02f * (1.0f - f.x);
            dfsum += ALPHA_F * f.y * ew; ew *= 1.02f * (1.0f - f.y);
            dfsum += ALPHA_F * f.z * ew; ew *= 1.02f * (1.0f - f.z);
            dfsum += ALPHA_F * f.w * ew; ew *= 1.02f * (1.0f - f.w);
        }
    }
    double Pbase_d = block_scan_excl((double)dfsum, tot, s_warp) + (double)INIT_LOGP_F;

    // pass 3: thresholds (q chain), screen, tcut, wv chain -> wvsum
    float wvsum = 0.0f;
    int tmax = 0;
    {
        float ew = __expf(Wbase);
        float q  = __expf((float)Pbase_d);
        float v  = __expf(Wbase * 0.001f);
#pragma unroll
        for (int k = 0; k < ELEMS / 4; k++) {
            float4 f = f4[(seg >> 2) + k];
            float4 c = c4[(seg >> 2) + k];
#pragma unroll
            for (int u = 0; u < 4; u++) {
                float fe = (u == 0) ? f.x : (u == 1) ? f.y : (u == 2) ? f.z : f.w;
                float ce = (u == 0) ? c.x : (u == 1) ? c.y : (u == 2) ? c.z : c.w;
                int i = seg + k * 4 + u;
                v *= exp_tiny(ce * 0.001f);
                if (i < T) {
                    float thr = q * (1.0f + q + q * q);     // = q/(1-q), q <= 1e-3
                    float T2  = thr - 1e-12f;
                    g_T2[i] = T2;
                    if ((i & (TCHUNK - 1)) == 0)            // T2 monotone decreasing
                        g_u2min[i / TCHUNK] = exp_tiny(-27.64f * T2) * (1.0f - 1e-5f);
                    if (q >= 1.4e-11f) tmax = i + 1;        // logit >= -25 (noise <= ~20)
                    wvsum += v;
                }
                float df = ALPHA_F * fe * ew;
                q = (q >= 1e-13f) ? q * exp_tiny(df) : 0.0f;
                ew *= 1.02f * (1.0f - fe);
            }
        }
    }
    double Sbase = block_scan_excl((double)wvsum, tot, s_warp);

    // pass 4: recompute wv chain, write exclusive prefix
    {
        float v = __expf(Wbase * 0.001f);
        float ls = 0.0f;
#pragma unroll
        for (int k = 0; k < ELEMS / 4; k++) {
            float4 c = c4[(seg >> 2) + k];
#pragma unroll
            for (int u = 0; u < 4; u++) {
                float ce = (u == 0) ? c.x : (u == 1) ? c.y : (u == 2) ? c.z : c.w;
                int i = seg + k * 4 + u;
                v *= exp_tiny(ce * 0.001f);
                if (i < T) {
                    g_prefix[i] = Sbase + (double)ls;
                    ls += v;
                }
            }
        }
    }
    if (tid == 0) g_prefix[T] = tot;

    // tcut block max-reduce
#pragma unroll
    for (int o = 16; o > 0; o >>= 1) tmax = max(tmax, __shfl_down_sync(0xffffffffu, tmax, o));
    if ((tid & 31) == 0) s_imax[tid >> 5] = tmax;
    __syncthreads();
    if (tid < NTH / 32) {
        int v = s_imax[tid];
#pragma unroll
        for (int o = (NTH / 64); o > 0; o >>= 1)
            v = max(v, __shfl_down_sync((1u << (NTH / 32)) - 1u, v, o));
        if (tid == 0) g_tcut = v;
    }
}

// ---------------------------------------------------------------------------
__device__ __forceinline__ void load_chunk(float4 v[TCHUNK], const float4* __restrict__ u2v,
                                           int tstart, int b4, int T, int B) {
#pragma unroll
    for (int t = 0; t < TCHUNK; t++)
        v[t] = (tstart + t < T) ? u2v[((size_t)(tstart + t) * B + b4) >> 2]
                                : make_float4(0.f, 0.f, 0.f, 0.f);
}

__device__ __forceinline__ void process_chunk(const float4 v[TCHUNK], int tstart, int b4,
                                              const float* __restrict__ u1,
                                              const float* __restrict__ u2,
                                              float u2min, int B) {
    unsigned m0 = 0, m1 = 0, m2 = 0, m3 = 0;
#pragma unroll
    for (int t = 0; t < TCHUNK; t++) {
        if (v[t].x > u2min) m0 |= 1u << t;
        if (v[t].y > u2min) m1 |= 1u << t;
        if (v[t].z > u2min) m2 |= 1u << t;
        if (v[t].w > u2min) m3 |= 1u << t;
    }
    const float EPSF = 1e-12f;
#pragma unroll
    for (int l = 0; l < 4; l++) {
        unsigned m = (l == 0) ? m0 : (l == 1) ? m1 : (l == 2) ? m2 : m3;
        if (m && g_death[b4 + l] > tstart) {
            while (m) {
                int t = __ffs(m) - 1;
                m &= m - 1;
                size_t idx = (size_t)(tstart + t) * B + b4 + l;
                float la = __logf(u2[idx] + EPSF);
                float lb = __logf(u1[idx] + EPSF);
                if (la > g_T2[tstart + t] * lb) {
                    atomicMin(&g_death[b4 + l], tstart + t);
                    break;              // bits ascend in t: first hit = chunk minimum
                }
            }
        }
    }
}

// ---------------------------------------------------------------------------
// Single fused kernel. Grid = (ceil(B/2048), GRIDY) = 148 blocks, 1 block/SM,
// all resident in wave 1 => internal flag-spins are deadlock-free.
__global__ void __launch_bounds__(NTH, 1)
k_all(const float* __restrict__ acts, const float* __restrict__ u1,
      const float* __restrict__ u2, float* __restrict__ out,
      int T, int B, int nelem, int nblocks) {
    int tid  = threadIdx.x;
    int flat = blockIdx.y * gridDim.x + blockIdx.x;
    bool producer = (flat == 0);

    // ---- Phase 1: wide elementwise + zero-pad to PADT (first nelem blocks) ----
    if (flat < nelem) {
        const float LOG_GAMMA_F = (float)log(1.02);
        int i = flat * NTH + tid;
        if (i < PADT) {
            float fv = 0.0f, cv = 0.0f;
            if (i < T) {
                fv = __expf(acts[i]);
                cv = LOG_GAMMA_F + __logf(1.0f - fv);
            }
            g_f[i] = fv;
            g_c[i] = cv;
        }
        if (i < B) g_death[i] = T;
        __syncthreads();
        if (tid == 0) { __threadfence(); atomicAdd(&g_elemdone, 1); }
    }

    int b4 = (blockIdx.x * NTH + tid) * 4;
    bool lanes_ok = (b4 + 3 < B);
    const float4* u2v = (const float4*)u2;

    if (producer) {
        // ---- Phase 2: scan bases / thresholds / prefix (this block only) ----
        if (tid == 0) { while (atomicAdd(&g_elemdone, 0) < nelem) __nanosleep(64); }
        __syncthreads();
        __threadfence();
        scanbases_body(T);
        __syncthreads();
        if (tid == 0) { __threadfence(); atomicExch(&g_flag, 1); }
        __syncthreads();
        // ---- Phase 3 (producer's chunks, normal loads) ----
        int tcut = g_tcut;
        for (int chunk = blockIdx.y; chunk * TCHUNK < tcut; chunk += gridDim.y) {
            if (lanes_ok) {
                float4 v[TCHUNK];
                load_chunk(v, u2v, chunk * TCHUNK, b4, T, B);
                process_chunk(v, chunk * TCHUNK, b4, u1, u2, g_u2min[chunk], B);
            }
        }
    } else {
        // ---- overlap: prefetch this block's first chunk while phase 2 runs ----
        float4 v[TCHUNK];
        int pchunk = blockIdx.y;
        if (lanes_ok) load_chunk(v, u2v, pchunk * TCHUNK, b4, T, B);
        if (tid == 0) {
            volatile int* vf = &g_flag;
            while (*vf == 0) __nanosleep(128);
        }
        __syncthreads();
        __threadfence();
        int tcut = g_tcut;
        if (lanes_ok && pchunk * TCHUNK < tcut)
            process_chunk(v, pchunk * TCHUNK, b4, u1, u2, g_u2min[pchunk], B);
        for (int chunk = pchunk + gridDim.y; chunk * TCHUNK < tcut; chunk += gridDim.y) {
            if (lanes_ok) {
                float4 w[TCHUNK];
                load_chunk(w, u2v, chunk * TCHUNK, b4, T, B);
                process_chunk(w, chunk * TCHUNK, b4, u1, u2, g_u2min[chunk], B);
            }
        }
    }

    // ---- Phase 4: last block reduces, then resets sync state for next replay ----
    __threadfence();
    __shared__ int lastFlag;
    if (tid == 0) lastFlag = (atomicAdd(&g_done, 1) == nblocks - 1);
    __syncthreads();
    if (!lastFlag) return;

    __shared__ double s_red[NTH / 32];
    double s = 0.0;
    for (int i = tid; i < B; i += NTH) s += g_prefix[g_death[i]];
#pragma unroll
    for (int o = 16; o > 0; o >>= 1) s += __shfl_down_sync(0xffffffffu, s, o);
    if ((tid & 31) == 0) s_red[tid >> 5] = s;
    __syncthreads();
    if (tid < NTH / 32) {
        double v = s_red[tid];
#pragma unroll
        for (int o = NTH / 64; o > 0; o >>= 1)
            v += __shfl_down_sync((1u << (NTH / 32)) - 1u, v, o);
        if (tid == 0) {
            out[0] = (float)(v / (double)B);
            g_flag = 0;                 // safe: all blocks already passed the flag wait
            g_elemdone = 0;
            g_done = 0;
        }
    }
}

extern "C" void kernel_launch(void* const* d_in, const int* in_sizes, int n_in,
                              void* d_out, int out_size) {
    const float* acts = (const float*)d_in[0];
    const float* u1   = (const float*)d_in[1];
    const float* u2   = (const float*)d_in[2];
    int T = in_sizes[0];
    int B = (T > 0) ? (in_sizes[1] / T) : 0;

    int gx = (B + NTH * 4 - 1) / (NTH * 4);           // 2 for B=4096
    dim3 grid(gx, GRIDY);                             // 148 blocks total
    int nblocks = gx * GRIDY;
    int maxTB = (T > B) ? T : B;
    int nelem = (maxTB + NTH - 1) / NTH;              // 20
    k_all<<<grid, NTH>>>(acts, u1, u2, (float*)d_out, T, B, nelem, nblocks);
}